// round 1
// baseline (speedup 1.0000x reference)
#include <cuda_runtime.h>
#include <math.h>

#define L_ 4
#define H_ 12
#define E_ 768
#define T_ 1024
#define B_ 4
#define V_ 50257
#define D_ 64
#define M_ (B_*T_)     // 4096
#define E3_ (3*E_)     // 2304
#define E4_ (4*E_)     // 3072

// ---------------- scratch (static device globals; no allocation) ----------
__device__ float g_x  [(size_t)M_*E_];
__device__ float g_h  [(size_t)M_*E_];
__device__ float g_qkv[(size_t)M_*E3_];
__device__ float g_att[(size_t)B_*H_*T_*T_];   // 50,331,648 floats
__device__ float g_y  [(size_t)M_*E_];
__device__ float g_fc [(size_t)M_*E4_];
__device__ float g_logp[B_*(T_-1)];            // 4092 per-row logp(label)

// ---------------- reductions ----------------------------------------------
__device__ __forceinline__ float blockReduceSum(float v, float* red) {
    int lane = threadIdx.x & 31, wid = threadIdx.x >> 5;
    #pragma unroll
    for (int o = 16; o; o >>= 1) v += __shfl_down_sync(0xffffffffu, v, o);
    __syncthreads();                // protect red across back-to-back calls
    if (lane == 0) red[wid] = v;
    __syncthreads();
    if (threadIdx.x == 0) {
        float s = 0.f;
        int nw = (blockDim.x + 31) >> 5;
        for (int i = 0; i < nw; i++) s += red[i];
        red[0] = s;
    }
    __syncthreads();
    return red[0];
}

__device__ __forceinline__ float blockReduceMax(float v, float* red) {
    int lane = threadIdx.x & 31, wid = threadIdx.x >> 5;
    #pragma unroll
    for (int o = 16; o; o >>= 1) v = fmaxf(v, __shfl_down_sync(0xffffffffu, v, o));
    __syncthreads();
    if (lane == 0) red[wid] = v;
    __syncthreads();
    if (threadIdx.x == 0) {
        float s = -1e30f;
        int nw = (blockDim.x + 31) >> 5;
        for (int i = 0; i < nw; i++) s = fmaxf(s, red[i]);
        red[0] = s;
    }
    __syncthreads();
    return red[0];
}

// ---------------- embedding -----------------------------------------------
__global__ void embed_kernel(const int* __restrict__ idx,
                             const float* __restrict__ wte,
                             const float* __restrict__ wpe) {
    int i = blockIdx.x * 256 + threadIdx.x;       // over M_*E_
    int bt = i / E_, e = i - bt * E_;
    int t = bt & (T_ - 1);
    g_x[i] = wte[(size_t)idx[bt] * E_ + e] + wpe[(size_t)t * E_ + e];
}

// ---------------- layernorm -----------------------------------------------
__global__ void ln_kernel(const float* __restrict__ in,
                          const float* __restrict__ w,
                          const float* __restrict__ b,
                          float* __restrict__ out) {
    int row = blockIdx.x;
    const float* x = in + (size_t)row * E_;
    __shared__ float sdata[E_];
    __shared__ float red[32];
    __shared__ float s_mean, s_rstd;
    float local = 0.f;
    for (int i = threadIdx.x; i < E_; i += 256) { float v = x[i]; sdata[i] = v; local += v; }
    float tot = blockReduceSum(local, red);
    if (threadIdx.x == 0) s_mean = tot * (1.0f / E_);
    __syncthreads();
    float m = s_mean, lv = 0.f;
    for (int i = threadIdx.x; i < E_; i += 256) { float d = sdata[i] - m; lv += d * d; }
    float var = blockReduceSum(lv, red);
    if (threadIdx.x == 0) s_rstd = rsqrtf(var * (1.0f / E_) + 1e-5f);
    __syncthreads();
    float r = s_rstd;
    float* o = out + (size_t)row * E_;
    for (int i = threadIdx.x; i < E_; i += 256)
        o[i] = (sdata[i] - m) * r * w[i] + b[i];
}

// ---------------- generic NT SGEMM: C = A[MxK] * B[NxK]^T (+bias,+gelu,+res)
#define BM 64
#define BN 64
#define BK 16

__global__ __launch_bounds__(256)
void gemm_nt(const float* __restrict__ A, const float* __restrict__ B,
             const float* __restrict__ bias, const float* __restrict__ res,
             float* __restrict__ C, int M, int N, int K, int gelu) {
    __shared__ float As[BK][BM + 1];
    __shared__ float Bs[BK][BN + 1];
    int tid = threadIdx.x;
    int m0 = blockIdx.y * BM, n0 = blockIdx.x * BN;
    int lr = tid >> 2;                 // 0..63
    int lk = (tid & 3) << 2;           // 0,4,8,12
    int tx = tid & 15, ty = tid >> 4;
    float acc[4][4] = {};

    for (int k0 = 0; k0 < K; k0 += BK) {
        float4 va = *(const float4*)(A + (size_t)(m0 + lr) * K + k0 + lk);
        As[lk + 0][lr] = va.x; As[lk + 1][lr] = va.y;
        As[lk + 2][lr] = va.z; As[lk + 3][lr] = va.w;
        int bn = n0 + lr;
        float4 vb = make_float4(0.f, 0.f, 0.f, 0.f);
        if (bn < N) vb = *(const float4*)(B + (size_t)bn * K + k0 + lk);
        Bs[lk + 0][lr] = vb.x; Bs[lk + 1][lr] = vb.y;
        Bs[lk + 2][lr] = vb.z; Bs[lk + 3][lr] = vb.w;
        __syncthreads();
        #pragma unroll
        for (int k = 0; k < BK; k++) {
            float a[4], bb[4];
            #pragma unroll
            for (int i = 0; i < 4; i++) a[i] = As[k][ty * 4 + i];
            #pragma unroll
            for (int j = 0; j < 4; j++) bb[j] = Bs[k][tx * 4 + j];
            #pragma unroll
            for (int i = 0; i < 4; i++)
                #pragma unroll
                for (int j = 0; j < 4; j++)
                    acc[i][j] += a[i] * bb[j];
        }
        __syncthreads();
    }

    #pragma unroll
    for (int i = 0; i < 4; i++) {
        int m = m0 + ty * 4 + i;
        #pragma unroll
        for (int j = 0; j < 4; j++) {
            int n = n0 + tx * 4 + j;
            if (n < N) {
                float v = acc[i][j];
                if (bias) v += bias[n];
                if (gelu) {
                    float t = v;
                    v = 0.5f * t * (1.0f + tanhf(0.7978845608028654f * (t + 0.044715f * t * t * t)));
                }
                size_t off = (size_t)m * N + n;
                if (res) v += res[off];
                C[off] = v;
            }
        }
    }
}

// ---------------- attention scores: S = Q K^T / sqrt(D) --------------------
__global__ __launch_bounds__(256)
void attn_scores(const float* __restrict__ qkv, float* __restrict__ att) {
    int bh = blockIdx.z;
    int b = bh / H_, h = bh % H_;
    int q0 = blockIdx.y * 32, k0 = blockIdx.x * 32;
    if (k0 > q0 + 31) return;                 // fully masked tile: never read
    __shared__ float Qs[32][65], Ks[32][65];
    int tid = threadIdx.x;
    int r = tid >> 3, c0 = (tid & 7) << 3;
    const float* qb = qkv + (size_t)(b * T_ + q0 + r) * E3_ + h * D_ + c0;
    const float* kb = qkv + (size_t)(b * T_ + k0 + r) * E3_ + E_ + h * D_ + c0;
    #pragma unroll
    for (int j = 0; j < 8; j++) { Qs[r][c0 + j] = qb[j]; Ks[r][c0 + j] = kb[j]; }
    __syncthreads();
    int tx = tid & 31, tyy = tid >> 5;        // tx = key, tyy = query group
    float acc[4] = {};
    #pragma unroll 8
    for (int d = 0; d < D_; d++) {
        float kv = Ks[tx][d];
        #pragma unroll
        for (int i = 0; i < 4; i++) acc[i] += Qs[tyy + 8 * i][d] * kv;
    }
    #pragma unroll
    for (int i = 0; i < 4; i++) {
        int q = q0 + tyy + 8 * i;
        att[((size_t)bh * T_ + q) * T_ + k0 + tx] = acc[i] * 0.125f;
    }
}

// ---------------- causal row softmax ---------------------------------------
__global__ void attn_softmax(float* __restrict__ att) {
    size_t row = blockIdx.x;
    int q = (int)(row & (T_ - 1));
    float* p = att + row * T_;
    int n = q + 1;
    __shared__ float red[32];
    float mx = -1e30f;
    for (int i = threadIdx.x; i < n; i += 256) mx = fmaxf(mx, p[i]);
    mx = blockReduceMax(mx, red);
    float s = 0.f;
    for (int i = threadIdx.x; i < n; i += 256) s += __expf(p[i] - mx);
    s = blockReduceSum(s, red);
    float inv = 1.0f / s;
    for (int i = threadIdx.x; i < n; i += 256) p[i] = __expf(p[i] - mx) * inv;
    for (int i = n + threadIdx.x; i < T_; i += 256) p[i] = 0.f;   // masked → 0
}

// ---------------- Y = att @ V ----------------------------------------------
__global__ __launch_bounds__(256)
void attn_v(const float* __restrict__ att, const float* __restrict__ qkv,
            float* __restrict__ y) {
    int bh = blockIdx.y;
    int b = bh / H_, h = bh % H_;
    int q0 = blockIdx.x * 32;
    __shared__ float Ps[32][33], Vs[32][65];
    int tid = threadIdx.x;
    int d = tid & 63, rq = tid >> 6;            // d col, 4 q groups
    int pr = tid >> 3, pc0 = (tid & 7) << 2;    // att tile loads
    int vc0 = (tid & 7) << 3;                   // v tile loads
    float acc[8] = {};
    for (int k0 = 0; k0 <= q0 + 31; k0 += 32) {
        const float* ap = att + ((size_t)bh * T_ + q0 + pr) * T_ + k0 + pc0;
        #pragma unroll
        for (int j = 0; j < 4; j++) Ps[pr][pc0 + j] = ap[j];
        const float* vp = qkv + (size_t)(b * T_ + k0 + pr) * E3_ + 2 * E_ + h * D_ + vc0;
        #pragma unroll
        for (int j = 0; j < 8; j++) Vs[pr][vc0 + j] = vp[j];
        __syncthreads();
        #pragma unroll 8
        for (int kk = 0; kk < 32; kk++) {
            float vv = Vs[kk][d];
            #pragma unroll
            for (int i = 0; i < 8; i++) acc[i] += Ps[rq + 4 * i][kk] * vv;
        }
        __syncthreads();
    }
    #pragma unroll
    for (int i = 0; i < 8; i++)
        y[(size_t)(b * T_ + q0 + rq + 4 * i) * E_ + h * D_ + d] = acc[i];
}

// ---------------- loss ------------------------------------------------------
__global__ void loss_rows(const float* __restrict__ logits,
                          const int* __restrict__ targets) {
    int r = blockIdx.x;                        // 0 .. B*(T-1)-1
    int b = r / (T_ - 1), t = r % (T_ - 1);
    const float* row = logits + (size_t)(b * T_ + t) * V_;
    int label = targets[b * T_ + t + 1];
    __shared__ float red[32];
    float mx = -1e30f;
    for (int i = threadIdx.x; i < V_; i += 256) mx = fmaxf(mx, row[i]);
    mx = blockReduceMax(mx, red);
    float s = 0.f;
    for (int i = threadIdx.x; i < V_; i += 256) s += __expf(row[i] - mx);
    s = blockReduceSum(s, red);
    if (threadIdx.x == 0)
        g_logp[r] = row[label] - mx - logf(s);
}

__global__ void loss_final(float* __restrict__ out, long long pos) {
    __shared__ float red[32];
    float s = 0.f;
    for (int i = threadIdx.x; i < B_ * (T_ - 1); i += 256) s += g_logp[i];
    s = blockReduceSum(s, red);
    if (threadIdx.x == 0) out[pos] = -s / (float)(B_ * (T_ - 1));
}

// ---------------- driver ----------------------------------------------------
extern "C" void kernel_launch(void* const* d_in, const int* in_sizes, int n_in,
                              void* d_out, int out_size) {
    const int*   idx     = (const int*)  d_in[0];
    const int*   targets = (const int*)  d_in[1];
    const float* wte     = (const float*)d_in[2];
    const float* wpe     = (const float*)d_in[3];
    const float* ln1_w   = (const float*)d_in[4];
    const float* ln1_b   = (const float*)d_in[5];
    const float* attn_w  = (const float*)d_in[6];
    const float* attn_b  = (const float*)d_in[7];
    const float* proj_w  = (const float*)d_in[8];
    const float* proj_b  = (const float*)d_in[9];
    const float* ln2_w   = (const float*)d_in[10];
    const float* ln2_b   = (const float*)d_in[11];
    const float* fc_w    = (const float*)d_in[12];
    const float* fc_b    = (const float*)d_in[13];
    const float* out_w   = (const float*)d_in[14];
    const float* out_b   = (const float*)d_in[15];
    const float* lnf_w   = (const float*)d_in[16];
    const float* lnf_b   = (const float*)d_in[17];
    float* out = (float*)d_out;

    float *x, *h, *qkv, *att, *y, *fc;
    cudaGetSymbolAddress((void**)&x,   g_x);
    cudaGetSymbolAddress((void**)&h,   g_h);
    cudaGetSymbolAddress((void**)&qkv, g_qkv);
    cudaGetSymbolAddress((void**)&att, g_att);
    cudaGetSymbolAddress((void**)&y,   g_y);
    cudaGetSymbolAddress((void**)&fc,  g_fc);

    embed_kernel<<<(M_ * E_) / 256, 256>>>(idx, wte, wpe);

    for (int l = 0; l < L_; l++) {
        ln_kernel<<<M_, 256>>>(x, ln1_w + (size_t)l * E_, ln1_b + (size_t)l * E_, h);
        gemm_nt<<<dim3(E3_ / BN, M_ / BM), 256>>>(
            h, attn_w + (size_t)l * E3_ * E_, attn_b + (size_t)l * E3_,
            nullptr, qkv, M_, E3_, E_, 0);
        attn_scores<<<dim3(T_ / 32, T_ / 32, B_ * H_), 256>>>(qkv, att);
        attn_softmax<<<B_ * H_ * T_, 256>>>(att);
        attn_v<<<dim3(T_ / 32, B_ * H_), 256>>>(att, qkv, y);
        gemm_nt<<<dim3(E_ / BN, M_ / BM), 256>>>(
            y, proj_w + (size_t)l * E_ * E_, proj_b + (size_t)l * E_,
            x, x, M_, E_, E_, 0);
        ln_kernel<<<M_, 256>>>(x, ln2_w + (size_t)l * E_, ln2_b + (size_t)l * E_, h);
        gemm_nt<<<dim3(E4_ / BN, M_ / BM), 256>>>(
            h, fc_w + (size_t)l * E4_ * E_, fc_b + (size_t)l * E4_,
            nullptr, fc, M_, E4_, E_, 1);
        gemm_nt<<<dim3(E_ / BN, M_ / BM), 256>>>(
            fc, out_w + (size_t)l * E_ * E4_, out_b + (size_t)l * E_,
            x, x, M_, E_, E4_, 0);
    }

    ln_kernel<<<M_, 256>>>(x, lnf_w, lnf_b, h);
    gemm_nt<<<dim3((V_ + BN - 1) / BN, M_ / BM), 256>>>(
        h, wte, nullptr, nullptr, out, M_, V_, E_, 0);

    loss_rows<<<B_ * (T_ - 1), 256>>>(out, targets);
    long long pos = (long long)M_ * V_;             // loss goes right after logits
    if (pos < (long long)out_size)
        loss_final<<<1, 256>>>(out, pos);
}

// round 2
// speedup vs baseline: 2.0719x; 2.0719x over previous
#include <cuda_runtime.h>
#include <math.h>

#define L_ 4
#define H_ 12
#define E_ 768
#define T_ 1024
#define B_ 4
#define V_ 50257
#define D_ 64
#define M_ (B_*T_)     // 4096
#define E3_ (3*E_)     // 2304
#define E4_ (4*E_)     // 3072

// ---------------- scratch (static device globals; no allocation) ----------
__device__ float g_x  [(size_t)M_*E_];
__device__ float g_h  [(size_t)M_*E_];
__device__ float g_qkv[(size_t)M_*E3_];
__device__ float g_att[(size_t)B_*H_*T_*T_];
__device__ float g_y  [(size_t)M_*E_];
__device__ float g_fc [(size_t)M_*E4_];
__device__ float g_logp[B_*(T_-1)];

// ---------------- reductions ----------------------------------------------
__device__ __forceinline__ float blockReduceSum(float v, float* red) {
    int lane = threadIdx.x & 31, wid = threadIdx.x >> 5;
    #pragma unroll
    for (int o = 16; o; o >>= 1) v += __shfl_down_sync(0xffffffffu, v, o);
    __syncthreads();
    if (lane == 0) red[wid] = v;
    __syncthreads();
    if (threadIdx.x == 0) {
        float s = 0.f;
        int nw = (blockDim.x + 31) >> 5;
        for (int i = 0; i < nw; i++) s += red[i];
        red[0] = s;
    }
    __syncthreads();
    return red[0];
}

__device__ __forceinline__ float blockReduceMax(float v, float* red) {
    int lane = threadIdx.x & 31, wid = threadIdx.x >> 5;
    #pragma unroll
    for (int o = 16; o; o >>= 1) v = fmaxf(v, __shfl_down_sync(0xffffffffu, v, o));
    __syncthreads();
    if (lane == 0) red[wid] = v;
    __syncthreads();
    if (threadIdx.x == 0) {
        float s = -1e30f;
        int nw = (blockDim.x + 31) >> 5;
        for (int i = 0; i < nw; i++) s = fmaxf(s, red[i]);
        red[0] = s;
    }
    __syncthreads();
    return red[0];
}

// ---------------- embedding -----------------------------------------------
__global__ void embed_kernel(const int* __restrict__ idx,
                             const float* __restrict__ wte,
                             const float* __restrict__ wpe) {
    int i = blockIdx.x * 256 + threadIdx.x;
    int bt = i / E_, e = i - bt * E_;
    int t = bt & (T_ - 1);
    g_x[i] = wte[(size_t)idx[bt] * E_ + e] + wpe[(size_t)t * E_ + e];
}

// ---------------- layernorm -----------------------------------------------
__global__ void ln_kernel(const float* __restrict__ in,
                          const float* __restrict__ w,
                          const float* __restrict__ b,
                          float* __restrict__ out) {
    int row = blockIdx.x;
    const float* x = in + (size_t)row * E_;
    __shared__ float sdata[E_];
    __shared__ float red[32];
    __shared__ float s_mean, s_rstd;
    float local = 0.f;
    for (int i = threadIdx.x; i < E_; i += 256) { float v = x[i]; sdata[i] = v; local += v; }
    float tot = blockReduceSum(local, red);
    if (threadIdx.x == 0) s_mean = tot * (1.0f / E_);
    __syncthreads();
    float m = s_mean, lv = 0.f;
    for (int i = threadIdx.x; i < E_; i += 256) { float d = sdata[i] - m; lv += d * d; }
    float var = blockReduceSum(lv, red);
    if (threadIdx.x == 0) s_rstd = rsqrtf(var * (1.0f / E_) + 1e-5f);
    __syncthreads();
    float r = s_rstd;
    float* o = out + (size_t)row * E_;
    for (int i = threadIdx.x; i < E_; i += 256)
        o[i] = (sdata[i] - m) * r * w[i] + b[i];
}

// ---------------- tf32 helpers ---------------------------------------------
__device__ __forceinline__ float to_tf32(float f) {
    unsigned r;
    asm("cvt.rna.tf32.f32 %0, %1;" : "=r"(r) : "f"(f));
    return __uint_as_float(r);
}

// ---------------- TF32 tensor-core NT GEMM: C = A[MxK] * B[NxK]^T -----------
// tile 128x64x16, 256 threads (8 warps), warp grid 4(m) x 2(n), 32x32 per warp
#define TBM 128
#define TBN 64
#define TBK 16
#define APAD 8
#define BPAD 8

__global__ __launch_bounds__(256)
void gemm_tf32(const float* __restrict__ A, const float* __restrict__ B,
               const float* __restrict__ bias, const float* __restrict__ res,
               float* __restrict__ C, int M, int N, int K, int gelu) {
    __shared__ float As[TBK][TBM + APAD];
    __shared__ float Bs[TBK][TBN + BPAD];
    int tid = threadIdx.x;
    int lane = tid & 31, wid = tid >> 5;
    int wm = wid & 3, wn = wid >> 2;
    int m0 = blockIdx.y * TBM, n0 = blockIdx.x * TBN;

    float acc[2][4][4];
    #pragma unroll
    for (int i = 0; i < 2; i++)
        #pragma unroll
        for (int j = 0; j < 4; j++)
            #pragma unroll
            for (int k = 0; k < 4; k++) acc[i][j][k] = 0.f;

    int la = lane & 3, lg = lane >> 2;   // frag col-in-k, row group

    for (int k0 = 0; k0 < K; k0 += TBK) {
        // load A: 128x16, 2 float4 per thread (coalesced along k)
        #pragma unroll
        for (int i = 0; i < 2; i++) {
            int idx = tid + i * 256;
            int row = idx >> 2, kc = (idx & 3) << 2;
            float4 v = *(const float4*)(A + (size_t)(m0 + row) * K + k0 + kc);
            As[kc + 0][row] = to_tf32(v.x);
            As[kc + 1][row] = to_tf32(v.y);
            As[kc + 2][row] = to_tf32(v.z);
            As[kc + 3][row] = to_tf32(v.w);
        }
        // load B: 64x16, 1 float4 per thread
        {
            int row = tid >> 2, kc = (tid & 3) << 2;
            int bn = n0 + row;
            float4 v = make_float4(0.f, 0.f, 0.f, 0.f);
            if (bn < N) v = *(const float4*)(B + (size_t)bn * K + k0 + kc);
            Bs[kc + 0][row] = to_tf32(v.x);
            Bs[kc + 1][row] = to_tf32(v.y);
            Bs[kc + 2][row] = to_tf32(v.z);
            Bs[kc + 3][row] = to_tf32(v.w);
        }
        __syncthreads();

        #pragma unroll
        for (int ks = 0; ks < TBK; ks += 8) {
            unsigned af[2][4], bf[4][2];
            #pragma unroll
            for (int mt = 0; mt < 2; mt++) {
                int rb = wm * 32 + mt * 16;
                af[mt][0] = __float_as_uint(As[ks + la    ][rb + lg    ]);
                af[mt][1] = __float_as_uint(As[ks + la    ][rb + lg + 8]);
                af[mt][2] = __float_as_uint(As[ks + la + 4][rb + lg    ]);
                af[mt][3] = __float_as_uint(As[ks + la + 4][rb + lg + 8]);
            }
            #pragma unroll
            for (int nt = 0; nt < 4; nt++) {
                int cb = wn * 32 + nt * 8;
                bf[nt][0] = __float_as_uint(Bs[ks + la    ][cb + lg]);
                bf[nt][1] = __float_as_uint(Bs[ks + la + 4][cb + lg]);
            }
            #pragma unroll
            for (int mt = 0; mt < 2; mt++)
                #pragma unroll
                for (int nt = 0; nt < 4; nt++) {
                    asm volatile(
                        "mma.sync.aligned.m16n8k8.row.col.f32.tf32.tf32.f32 "
                        "{%0,%1,%2,%3}, {%4,%5,%6,%7}, {%8,%9}, {%0,%1,%2,%3};"
                        : "+f"(acc[mt][nt][0]), "+f"(acc[mt][nt][1]),
                          "+f"(acc[mt][nt][2]), "+f"(acc[mt][nt][3])
                        : "r"(af[mt][0]), "r"(af[mt][1]), "r"(af[mt][2]), "r"(af[mt][3]),
                          "r"(bf[nt][0]), "r"(bf[nt][1]));
                }
        }
        __syncthreads();
    }

    // epilogue
    #pragma unroll
    for (int mt = 0; mt < 2; mt++) {
        int rbase = m0 + wm * 32 + mt * 16 + lg;
        #pragma unroll
        for (int nt = 0; nt < 4; nt++) {
            int cbase = n0 + wn * 32 + nt * 8 + la * 2;
            #pragma unroll
            for (int half = 0; half < 2; half++) {
                int r = rbase + half * 8;
                #pragma unroll
                for (int cc = 0; cc < 2; cc++) {
                    int c = cbase + cc;
                    if (c < N) {
                        float v = acc[mt][nt][half * 2 + cc];
                        if (bias) v += bias[c];
                        if (gelu) {
                            float t = v;
                            v = 0.5f * t * (1.0f + tanhf(0.7978845608028654f *
                                    (t + 0.044715f * t * t * t)));
                        }
                        size_t off = (size_t)r * N + c;
                        if (res) v += res[off];
                        C[off] = v;
                    }
                }
            }
        }
    }
}

// ---------------- attention scores: S = Q K^T / sqrt(D) --------------------
__global__ __launch_bounds__(256)
void attn_scores(const float* __restrict__ qkv, float* __restrict__ att) {
    int bh = blockIdx.z;
    int b = bh / H_, h = bh % H_;
    int q0 = blockIdx.y * 32, k0 = blockIdx.x * 32;
    if (k0 > q0 + 31) return;
    __shared__ float Qs[32][65], Ks[32][65];
    int tid = threadIdx.x;
    int r = tid >> 3, c0 = (tid & 7) << 3;
    const float* qb = qkv + (size_t)(b * T_ + q0 + r) * E3_ + h * D_ + c0;
    const float* kb = qkv + (size_t)(b * T_ + k0 + r) * E3_ + E_ + h * D_ + c0;
    #pragma unroll
    for (int j = 0; j < 8; j++) { Qs[r][c0 + j] = qb[j]; Ks[r][c0 + j] = kb[j]; }
    __syncthreads();
    int tx = tid & 31, tyy = tid >> 5;
    float acc[4] = {};
    #pragma unroll 8
    for (int d = 0; d < D_; d++) {
        float kv = Ks[tx][d];
        #pragma unroll
        for (int i = 0; i < 4; i++) acc[i] += Qs[tyy + 8 * i][d] * kv;
    }
    #pragma unroll
    for (int i = 0; i < 4; i++) {
        int q = q0 + tyy + 8 * i;
        att[((size_t)bh * T_ + q) * T_ + k0 + tx] = acc[i] * 0.125f;
    }
}

// ---------------- causal row softmax ---------------------------------------
__global__ void attn_softmax(float* __restrict__ att) {
    size_t row = blockIdx.x;
    int q = (int)(row & (T_ - 1));
    float* p = att + row * T_;
    int n = q + 1;
    __shared__ float red[32];
    float mx = -1e30f;
    for (int i = threadIdx.x; i < n; i += 256) mx = fmaxf(mx, p[i]);
    mx = blockReduceMax(mx, red);
    float s = 0.f;
    for (int i = threadIdx.x; i < n; i += 256) s += __expf(p[i] - mx);
    s = blockReduceSum(s, red);
    float inv = 1.0f / s;
    for (int i = threadIdx.x; i < n; i += 256) p[i] = __expf(p[i] - mx) * inv;
    for (int i = n + threadIdx.x; i < T_; i += 256) p[i] = 0.f;
}

// ---------------- Y = att @ V ----------------------------------------------
__global__ __launch_bounds__(256)
void attn_v(const float* __restrict__ att, const float* __restrict__ qkv,
            float* __restrict__ y) {
    int bh = blockIdx.y;
    int b = bh / H_, h = bh % H_;
    int q0 = blockIdx.x * 32;
    __shared__ float Ps[32][33], Vs[32][65];
    int tid = threadIdx.x;
    int d = tid & 63, rq = tid >> 6;
    int pr = tid >> 3, pc0 = (tid & 7) << 2;
    int vc0 = (tid & 7) << 3;
    float acc[8] = {};
    for (int k0 = 0; k0 <= q0 + 31; k0 += 32) {
        const float* ap = att + ((size_t)bh * T_ + q0 + pr) * T_ + k0 + pc0;
        #pragma unroll
        for (int j = 0; j < 4; j++) Ps[pr][pc0 + j] = ap[j];
        const float* vp = qkv + (size_t)(b * T_ + k0 + pr) * E3_ + 2 * E_ + h * D_ + vc0;
        #pragma unroll
        for (int j = 0; j < 8; j++) Vs[pr][vc0 + j] = vp[j];
        __syncthreads();
        #pragma unroll 8
        for (int kk = 0; kk < 32; kk++) {
            float vv = Vs[kk][d];
            #pragma unroll
            for (int i = 0; i < 8; i++) acc[i] += Ps[rq + 4 * i][kk] * vv;
        }
        __syncthreads();
    }
    #pragma unroll
    for (int i = 0; i < 8; i++)
        y[(size_t)(b * T_ + q0 + rq + 4 * i) * E_ + h * D_ + d] = acc[i];
}

// ---------------- loss ------------------------------------------------------
__global__ void loss_rows(const float* __restrict__ logits,
                          const int* __restrict__ targets) {
    int r = blockIdx.x;
    int b = r / (T_ - 1), t = r % (T_ - 1);
    const float* row = logits + (size_t)(b * T_ + t) * V_;
    int label = targets[b * T_ + t + 1];
    __shared__ float red[32];
    float mx = -1e30f;
    for (int i = threadIdx.x; i < V_; i += 256) mx = fmaxf(mx, row[i]);
    mx = blockReduceMax(mx, red);
    float s = 0.f;
    for (int i = threadIdx.x; i < V_; i += 256) s += __expf(row[i] - mx);
    s = blockReduceSum(s, red);
    if (threadIdx.x == 0)
        g_logp[r] = row[label] - mx - logf(s);
}

__global__ void loss_final(float* __restrict__ out, long long pos) {
    __shared__ float red[32];
    float s = 0.f;
    for (int i = threadIdx.x; i < B_ * (T_ - 1); i += 256) s += g_logp[i];
    s = blockReduceSum(s, red);
    if (threadIdx.x == 0) out[pos] = -s / (float)(B_ * (T_ - 1));
}

// ---------------- driver ----------------------------------------------------
extern "C" void kernel_launch(void* const* d_in, const int* in_sizes, int n_in,
                              void* d_out, int out_size) {
    const int*   idx     = (const int*)  d_in[0];
    const int*   targets = (const int*)  d_in[1];
    const float* wte     = (const float*)d_in[2];
    const float* wpe     = (const float*)d_in[3];
    const float* ln1_w   = (const float*)d_in[4];
    const float* ln1_b   = (const float*)d_in[5];
    const float* attn_w  = (const float*)d_in[6];
    const float* attn_b  = (const float*)d_in[7];
    const float* proj_w  = (const float*)d_in[8];
    const float* proj_b  = (const float*)d_in[9];
    const float* ln2_w   = (const float*)d_in[10];
    const float* ln2_b   = (const float*)d_in[11];
    const float* fc_w    = (const float*)d_in[12];
    const float* fc_b    = (const float*)d_in[13];
    const float* out_w   = (const float*)d_in[14];
    const float* out_b   = (const float*)d_in[15];
    const float* lnf_w   = (const float*)d_in[16];
    const float* lnf_b   = (const float*)d_in[17];
    float* out = (float*)d_out;

    float *x, *h, *qkv, *att, *y, *fc;
    cudaGetSymbolAddress((void**)&x,   g_x);
    cudaGetSymbolAddress((void**)&h,   g_h);
    cudaGetSymbolAddress((void**)&qkv, g_qkv);
    cudaGetSymbolAddress((void**)&att, g_att);
    cudaGetSymbolAddress((void**)&y,   g_y);
    cudaGetSymbolAddress((void**)&fc,  g_fc);

    embed_kernel<<<(M_ * E_) / 256, 256>>>(idx, wte, wpe);

    for (int l = 0; l < L_; l++) {
        ln_kernel<<<M_, 256>>>(x, ln1_w + (size_t)l * E_, ln1_b + (size_t)l * E_, h);
        gemm_tf32<<<dim3(E3_ / TBN, M_ / TBM), 256>>>(
            h, attn_w + (size_t)l * E3_ * E_, attn_b + (size_t)l * E3_,
            nullptr, qkv, M_, E3_, E_, 0);
        attn_scores<<<dim3(T_ / 32, T_ / 32, B_ * H_), 256>>>(qkv, att);
        attn_softmax<<<B_ * H_ * T_, 256>>>(att);
        attn_v<<<dim3(T_ / 32, B_ * H_), 256>>>(att, qkv, y);
        gemm_tf32<<<dim3(E_ / TBN, M_ / TBM), 256>>>(
            y, proj_w + (size_t)l * E_ * E_, proj_b + (size_t)l * E_,
            x, x, M_, E_, E_, 0);
        ln_kernel<<<M_, 256>>>(x, ln2_w + (size_t)l * E_, ln2_b + (size_t)l * E_, h);
        gemm_tf32<<<dim3(E4_ / TBN, M_ / TBM), 256>>>(
            h, fc_w + (size_t)l * E4_ * E_, fc_b + (size_t)l * E4_,
            nullptr, fc, M_, E4_, E_, 1);
        gemm_tf32<<<dim3(E_ / TBN, M_ / TBM), 256>>>(
            fc, out_w + (size_t)l * E_ * E4_, out_b + (size_t)l * E_,
            x, x, M_, E_, E4_, 0);
    }

    ln_kernel<<<M_, 256>>>(x, lnf_w, lnf_b, h);
    gemm_tf32<<<dim3((V_ + TBN - 1) / TBN, M_ / TBM), 256>>>(
        h, wte, nullptr, nullptr, out, M_, V_, E_, 0);

    loss_rows<<<B_ * (T_ - 1), 256>>>(out, targets);
    long long pos = (long long)M_ * V_;
    if (pos < (long long)out_size)
        loss_final<<<1, 256>>>(out, pos);
}

// round 3
// speedup vs baseline: 3.1600x; 1.5252x over previous
#include <cuda_runtime.h>
#include <math.h>

#define L_ 4
#define H_ 12
#define E_ 768
#define T_ 1024
#define B_ 4
#define V_ 50257
#define D_ 64
#define M_ (B_*T_)     // 4096
#define E3_ (3*E_)     // 2304
#define E4_ (4*E_)     // 3072

// ---------------- scratch (static device globals; no allocation) ----------
__device__ float g_x  [(size_t)M_*E_];
__device__ float g_h  [(size_t)M_*E_];
__device__ float g_qkv[(size_t)M_*E3_];
__device__ float g_y  [(size_t)M_*E_];
__device__ float g_fc [(size_t)M_*E4_];
__device__ float g_logp[B_*(T_-1)];

// ---------------- reductions ----------------------------------------------
__device__ __forceinline__ float blockReduceSum(float v, float* red) {
    int lane = threadIdx.x & 31, wid = threadIdx.x >> 5;
    #pragma unroll
    for (int o = 16; o; o >>= 1) v += __shfl_down_sync(0xffffffffu, v, o);
    __syncthreads();
    if (lane == 0) red[wid] = v;
    __syncthreads();
    if (threadIdx.x == 0) {
        float s = 0.f;
        int nw = (blockDim.x + 31) >> 5;
        for (int i = 0; i < nw; i++) s += red[i];
        red[0] = s;
    }
    __syncthreads();
    return red[0];
}

__device__ __forceinline__ float blockReduceMax(float v, float* red) {
    int lane = threadIdx.x & 31, wid = threadIdx.x >> 5;
    #pragma unroll
    for (int o = 16; o; o >>= 1) v = fmaxf(v, __shfl_down_sync(0xffffffffu, v, o));
    __syncthreads();
    if (lane == 0) red[wid] = v;
    __syncthreads();
    if (threadIdx.x == 0) {
        float s = -1e30f;
        int nw = (blockDim.x + 31) >> 5;
        for (int i = 0; i < nw; i++) s = fmaxf(s, red[i]);
        red[0] = s;
    }
    __syncthreads();
    return red[0];
}

// ---------------- tf32 helpers ---------------------------------------------
__device__ __forceinline__ float to_tf32(float f) {
    unsigned r;
    asm("cvt.rna.tf32.f32 %0, %1;" : "=r"(r) : "f"(f));
    return __uint_as_float(r);
}

__device__ __forceinline__ void split_tf32(float x, unsigned& hi, unsigned& lo) {
    float h = to_tf32(x);
    hi = __float_as_uint(h);
    lo = __float_as_uint(to_tf32(x - h));
}

#define MMA_TF32(acc, a0,a1,a2,a3, b0,b1)                                   \
    asm volatile(                                                            \
        "mma.sync.aligned.m16n8k8.row.col.f32.tf32.tf32.f32 "               \
        "{%0,%1,%2,%3}, {%4,%5,%6,%7}, {%8,%9}, {%0,%1,%2,%3};"             \
        : "+f"((acc)[0]), "+f"((acc)[1]), "+f"((acc)[2]), "+f"((acc)[3])    \
        : "r"(a0), "r"(a1), "r"(a2), "r"(a3), "r"(b0), "r"(b1))

// ---------------- embedding -----------------------------------------------
__global__ void embed_kernel(const int* __restrict__ idx,
                             const float* __restrict__ wte,
                             const float* __restrict__ wpe) {
    int i = blockIdx.x * 256 + threadIdx.x;
    int bt = i / E_, e = i - bt * E_;
    int t = bt & (T_ - 1);
    g_x[i] = wte[(size_t)idx[bt] * E_ + e] + wpe[(size_t)t * E_ + e];
}

// ---------------- layernorm -----------------------------------------------
__global__ void ln_kernel(const float* __restrict__ in,
                          const float* __restrict__ w,
                          const float* __restrict__ b,
                          float* __restrict__ out) {
    int row = blockIdx.x;
    const float* x = in + (size_t)row * E_;
    __shared__ float sdata[E_];
    __shared__ float red[32];
    __shared__ float s_mean, s_rstd;
    float local = 0.f;
    for (int i = threadIdx.x; i < E_; i += 256) { float v = x[i]; sdata[i] = v; local += v; }
    float tot = blockReduceSum(local, red);
    if (threadIdx.x == 0) s_mean = tot * (1.0f / E_);
    __syncthreads();
    float m = s_mean, lv = 0.f;
    for (int i = threadIdx.x; i < E_; i += 256) { float d = sdata[i] - m; lv += d * d; }
    float var = blockReduceSum(lv, red);
    if (threadIdx.x == 0) s_rstd = rsqrtf(var * (1.0f / E_) + 1e-5f);
    __syncthreads();
    float r = s_rstd;
    float* o = out + (size_t)row * E_;
    for (int i = threadIdx.x; i < E_; i += 256)
        o[i] = (sdata[i] - m) * r * w[i] + b[i];
}

// ---------------- TF32 GEMM: C = A[MxK] * B[NxK]^T, 128x128x16 2-stage -----
// 256 threads, 8 warps (2 m x 4 n), warp tile 64x32
__global__ __launch_bounds__(256)
void gemm_tf32(const float* __restrict__ A, const float* __restrict__ B,
               const float* __restrict__ bias, const float* __restrict__ res,
               float* __restrict__ C, int M, int N, int K, int gelu) {
    __shared__ float As[2][16][136];
    __shared__ float Bs[2][16][136];

    int nbn = (N + 127) >> 7;
    int bid = blockIdx.x;
    int bpg = 8 * nbn;                      // 8 m-rows per group
    int g = bid / bpg, r = bid % bpg;
    int m0 = (g * 8 + (r & 7)) << 7;
    int n0 = (r >> 3) << 7;

    int tid = threadIdx.x;
    int lane = tid & 31, wid = tid >> 5;
    int wm = wid >> 2, wn = wid & 3;        // 2 x 4 warps
    int la = lane & 3, lg = lane >> 2;

    float acc[4][4][4];
    #pragma unroll
    for (int i = 0; i < 4; i++)
        #pragma unroll
        for (int j = 0; j < 4; j++)
            #pragma unroll
            for (int k = 0; k < 4; k++) acc[i][j][k] = 0.f;

    int a_row[2], a_kc[2];
    #pragma unroll
    for (int i = 0; i < 2; i++) {
        int id = tid + i * 256;
        a_row[i] = id >> 2;
        a_kc[i]  = (id & 3) << 2;
    }

    float4 pa[2], pb[2];
    // prologue: tile 0
    #pragma unroll
    for (int i = 0; i < 2; i++) {
        pa[i] = *(const float4*)(A + (size_t)(m0 + a_row[i]) * K + a_kc[i]);
        int bn = n0 + a_row[i];
        pb[i] = (bn < N) ? *(const float4*)(B + (size_t)bn * K + a_kc[i])
                         : make_float4(0.f, 0.f, 0.f, 0.f);
    }
    #pragma unroll
    for (int i = 0; i < 2; i++) {
        As[0][a_kc[i] + 0][a_row[i]] = to_tf32(pa[i].x);
        As[0][a_kc[i] + 1][a_row[i]] = to_tf32(pa[i].y);
        As[0][a_kc[i] + 2][a_row[i]] = to_tf32(pa[i].z);
        As[0][a_kc[i] + 3][a_row[i]] = to_tf32(pa[i].w);
        Bs[0][a_kc[i] + 0][a_row[i]] = to_tf32(pb[i].x);
        Bs[0][a_kc[i] + 1][a_row[i]] = to_tf32(pb[i].y);
        Bs[0][a_kc[i] + 2][a_row[i]] = to_tf32(pb[i].z);
        Bs[0][a_kc[i] + 3][a_row[i]] = to_tf32(pb[i].w);
    }
    __syncthreads();

    int nk = K >> 4;
    for (int kt = 0; kt < nk; kt++) {
        int cur = kt & 1;
        if (kt + 1 < nk) {
            int kb = (kt + 1) << 4;
            #pragma unroll
            for (int i = 0; i < 2; i++) {
                pa[i] = *(const float4*)(A + (size_t)(m0 + a_row[i]) * K + kb + a_kc[i]);
                int bn = n0 + a_row[i];
                pb[i] = (bn < N) ? *(const float4*)(B + (size_t)bn * K + kb + a_kc[i])
                                 : make_float4(0.f, 0.f, 0.f, 0.f);
            }
        }
        #pragma unroll
        for (int ks = 0; ks < 16; ks += 8) {
            unsigned af[4][4], bf[4][2];
            #pragma unroll
            for (int mt = 0; mt < 4; mt++) {
                int rb = wm * 64 + mt * 16;
                af[mt][0] = __float_as_uint(As[cur][ks + la    ][rb + lg    ]);
                af[mt][1] = __float_as_uint(As[cur][ks + la    ][rb + lg + 8]);
                af[mt][2] = __float_as_uint(As[cur][ks + la + 4][rb + lg    ]);
                af[mt][3] = __float_as_uint(As[cur][ks + la + 4][rb + lg + 8]);
            }
            #pragma unroll
            for (int nt = 0; nt < 4; nt++) {
                int cb = wn * 32 + nt * 8;
                bf[nt][0] = __float_as_uint(Bs[cur][ks + la    ][cb + lg]);
                bf[nt][1] = __float_as_uint(Bs[cur][ks + la + 4][cb + lg]);
            }
            #pragma unroll
            for (int mt = 0; mt < 4; mt++)
                #pragma unroll
                for (int nt = 0; nt < 4; nt++)
                    MMA_TF32(acc[mt][nt], af[mt][0], af[mt][1], af[mt][2], af[mt][3],
                             bf[nt][0], bf[nt][1]);
        }
        if (kt + 1 < nk) {
            int nxt = cur ^ 1;
            #pragma unroll
            for (int i = 0; i < 2; i++) {
                As[nxt][a_kc[i] + 0][a_row[i]] = to_tf32(pa[i].x);
                As[nxt][a_kc[i] + 1][a_row[i]] = to_tf32(pa[i].y);
                As[nxt][a_kc[i] + 2][a_row[i]] = to_tf32(pa[i].z);
                As[nxt][a_kc[i] + 3][a_row[i]] = to_tf32(pa[i].w);
                Bs[nxt][a_kc[i] + 0][a_row[i]] = to_tf32(pb[i].x);
                Bs[nxt][a_kc[i] + 1][a_row[i]] = to_tf32(pb[i].y);
                Bs[nxt][a_kc[i] + 2][a_row[i]] = to_tf32(pb[i].z);
                Bs[nxt][a_kc[i] + 3][a_row[i]] = to_tf32(pb[i].w);
            }
            __syncthreads();
        }
    }

    // epilogue
    #pragma unroll
    for (int mt = 0; mt < 4; mt++) {
        int rbase = m0 + wm * 64 + mt * 16 + lg;
        #pragma unroll
        for (int nt = 0; nt < 4; nt++) {
            int cbase = n0 + wn * 32 + nt * 8 + la * 2;
            #pragma unroll
            for (int half = 0; half < 2; half++) {
                int rr = rbase + half * 8;
                #pragma unroll
                for (int cc = 0; cc < 2; cc++) {
                    int c = cbase + cc;
                    if (c < N) {
                        float v = acc[mt][nt][half * 2 + cc];
                        if (bias) v += bias[c];
                        if (gelu) {
                            float t = v;
                            v = 0.5f * t * (1.0f + tanhf(0.7978845608028654f *
                                    (t + 0.044715f * t * t * t)));
                        }
                        size_t off = (size_t)rr * N + c;
                        if (res) v += res[off];
                        C[off] = v;
                    }
                }
            }
        }
    }
}

// ---------------- fused flash attention (3xTF32 mma, online softmax) -------
// block = 128 threads (4 warps), one (b,h) x 64 q-rows. k-tiles of 64.
#define FATT_SMEM ((4 * 64 * 68 + 3 * 64) * 4)

__global__ __launch_bounds__(128)
void flash_attn(const float* __restrict__ qkv, float* __restrict__ y) {
    extern __shared__ float fsm[];
    float (*Qs)[68] = (float(*)[68])(fsm);
    float (*Ks)[68] = (float(*)[68])(fsm + 64 * 68);
    float (*Vs)[68] = (float(*)[68])(fsm + 2 * 64 * 68);
    float (*Ps)[68] = (float(*)[68])(fsm + 3 * 64 * 68);
    float* m_s = fsm + 4 * 64 * 68;
    float* l_s = m_s + 64;
    float* alpha_s = l_s + 64;

    int bh = blockIdx.y;
    int b = bh / H_, h = bh % H_;
    int q0 = blockIdx.x * 64;
    int tid = threadIdx.x;
    int lane = tid & 31, wm = tid >> 5;     // warp = 16 q rows
    int la = lane & 3, lg = lane >> 2;

    // load Q tile [64 q][64 d]
    #pragma unroll
    for (int i = 0; i < 8; i++) {
        int f4 = tid + i * 128;
        int row = f4 >> 4, c = (f4 & 15) << 2;
        *(float4*)&Qs[row][c] =
            *(const float4*)(qkv + (size_t)(b * T_ + q0 + row) * E3_ + h * D_ + c);
    }
    if (tid < 64) { m_s[tid] = -1e30f; l_s[tid] = 0.f; }

    float acc_o[8][4];
    #pragma unroll
    for (int i = 0; i < 8; i++)
        #pragma unroll
        for (int j = 0; j < 4; j++) acc_o[i][j] = 0.f;

    int row0 = wm * 16 + lg;                // this thread's two q rows (frag)
    int row1 = row0 + 8;

    int ktiles = (q0 >> 6) + 1;
    for (int kt = 0; kt < ktiles; kt++) {
        int k0 = kt << 6;
        __syncthreads();    // prior iteration finished reading Ks/Vs/Ps
        #pragma unroll
        for (int i = 0; i < 8; i++) {
            int f4 = tid + i * 128;
            int row = f4 >> 4, c = (f4 & 15) << 2;
            const float* base = qkv + (size_t)(b * T_ + k0 + row) * E3_ + h * D_ + c;
            *(float4*)&Ks[row][c] = *(const float4*)(base + E_);
            *(float4*)&Vs[row][c] = *(const float4*)(base + 2 * E_);
        }
        __syncthreads();

        // ---- S = Q K^T (3xTF32) ----
        float acc_s[8][4];
        #pragma unroll
        for (int i = 0; i < 8; i++)
            #pragma unroll
            for (int j = 0; j < 4; j++) acc_s[i][j] = 0.f;

        #pragma unroll
        for (int ks = 0; ks < 64; ks += 8) {
            unsigned ah[4], al[4];
            split_tf32(Qs[row0][ks + la    ], ah[0], al[0]);
            split_tf32(Qs[row1][ks + la    ], ah[1], al[1]);
            split_tf32(Qs[row0][ks + la + 4], ah[2], al[2]);
            split_tf32(Qs[row1][ks + la + 4], ah[3], al[3]);
            #pragma unroll
            for (int nt = 0; nt < 8; nt++) {
                int cb = nt * 8;
                unsigned bh0, bl0, bh1, bl1;
                split_tf32(Ks[cb + lg][ks + la    ], bh0, bl0);
                split_tf32(Ks[cb + lg][ks + la + 4], bh1, bl1);
                MMA_TF32(acc_s[nt], al[0], al[1], al[2], al[3], bh0, bh1);
                MMA_TF32(acc_s[nt], ah[0], ah[1], ah[2], ah[3], bl0, bl1);
                MMA_TF32(acc_s[nt], ah[0], ah[1], ah[2], ah[3], bh0, bh1);
            }
        }
        // mask + scale, write to Ps
        #pragma unroll
        for (int nt = 0; nt < 8; nt++) {
            int cb = nt * 8 + 2 * la;
            #pragma unroll
            for (int rr = 0; rr < 2; rr++) {
                int rloc = rr ? row1 : row0;
                int grow = q0 + rloc;
                #pragma unroll
                for (int cc = 0; cc < 2; cc++) {
                    int gcol = k0 + cb + cc;
                    float v = acc_s[nt][rr * 2 + cc] * 0.125f;
                    if (gcol > grow) v = -1e30f;
                    Ps[rloc][cb + cc] = v;
                }
            }
        }
        __syncthreads();

        // ---- online softmax on Ps (2 threads per row) ----
        {
            int r = tid >> 1, half = tid & 1;
            int c0 = half * 32;
            float mx = -1e30f;
            #pragma unroll 8
            for (int c = 0; c < 32; c++) mx = fmaxf(mx, Ps[r][c0 + c]);
            mx = fmaxf(mx, __shfl_xor_sync(0xffffffffu, mx, 1));
            float m_new = fmaxf(m_s[r], mx);
            float s = 0.f;
            #pragma unroll 8
            for (int c = 0; c < 32; c++) {
                float p = __expf(Ps[r][c0 + c] - m_new);
                Ps[r][c0 + c] = p;
                s += p;
            }
            s += __shfl_xor_sync(0xffffffffu, s, 1);
            if (half == 0) {
                float alpha = __expf(m_s[r] - m_new);
                l_s[r] = l_s[r] * alpha + s;
                m_s[r] = m_new;
                alpha_s[r] = alpha;
            }
        }
        __syncthreads();

        // ---- rescale O, then O += P V (3xTF32) ----
        {
            float a0 = alpha_s[row0], a1 = alpha_s[row1];
            #pragma unroll
            for (int nt = 0; nt < 8; nt++) {
                acc_o[nt][0] *= a0; acc_o[nt][1] *= a0;
                acc_o[nt][2] *= a1; acc_o[nt][3] *= a1;
            }
        }
        #pragma unroll
        for (int ks = 0; ks < 64; ks += 8) {
            unsigned ah[4], al[4];
            split_tf32(Ps[row0][ks + la    ], ah[0], al[0]);
            split_tf32(Ps[row1][ks + la    ], ah[1], al[1]);
            split_tf32(Ps[row0][ks + la + 4], ah[2], al[2]);
            split_tf32(Ps[row1][ks + la + 4], ah[3], al[3]);
            #pragma unroll
            for (int nt = 0; nt < 8; nt++) {
                int cb = nt * 8;
                unsigned bh0, bl0, bh1, bl1;
                split_tf32(Vs[ks + la    ][cb + lg], bh0, bl0);
                split_tf32(Vs[ks + la + 4][cb + lg], bh1, bl1);
                MMA_TF32(acc_o[nt], al[0], al[1], al[2], al[3], bh0, bh1);
                MMA_TF32(acc_o[nt], ah[0], ah[1], ah[2], ah[3], bl0, bl1);
                MMA_TF32(acc_o[nt], ah[0], ah[1], ah[2], ah[3], bh0, bh1);
            }
        }
    }

    // epilogue: normalize, store
    float inv0 = 1.0f / l_s[row0];
    float inv1 = 1.0f / l_s[row1];
    size_t yb0 = (size_t)(b * T_ + q0 + row0) * E_ + h * D_;
    size_t yb1 = (size_t)(b * T_ + q0 + row1) * E_ + h * D_;
    #pragma unroll
    for (int nt = 0; nt < 8; nt++) {
        int cb = nt * 8 + 2 * la;
        y[yb0 + cb    ] = acc_o[nt][0] * inv0;
        y[yb0 + cb + 1] = acc_o[nt][1] * inv0;
        y[yb1 + cb    ] = acc_o[nt][2] * inv1;
        y[yb1 + cb + 1] = acc_o[nt][3] * inv1;
    }
}

// ---------------- loss ------------------------------------------------------
__global__ void loss_rows(const float* __restrict__ logits,
                          const int* __restrict__ targets) {
    int r = blockIdx.x;
    int b = r / (T_ - 1), t = r % (T_ - 1);
    const float* row = logits + (size_t)(b * T_ + t) * V_;
    int label = targets[b * T_ + t + 1];
    __shared__ float red[32];
    float mx = -1e30f;
    for (int i = threadIdx.x; i < V_; i += 256) mx = fmaxf(mx, row[i]);
    mx = blockReduceMax(mx, red);
    float s = 0.f;
    for (int i = threadIdx.x; i < V_; i += 256) s += __expf(row[i] - mx);
    s = blockReduceSum(s, red);
    if (threadIdx.x == 0)
        g_logp[r] = row[label] - mx - logf(s);
}

__global__ void loss_final(float* __restrict__ out, long long pos) {
    __shared__ float red[32];
    float s = 0.f;
    for (int i = threadIdx.x; i < B_ * (T_ - 1); i += 256) s += g_logp[i];
    s = blockReduceSum(s, red);
    if (threadIdx.x == 0) out[pos] = -s / (float)(B_ * (T_ - 1));
}

// ---------------- driver ----------------------------------------------------
static inline int gemm_grid(int M, int N) {
    return (M >> 7) * ((N + 127) >> 7);
}

extern "C" void kernel_launch(void* const* d_in, const int* in_sizes, int n_in,
                              void* d_out, int out_size) {
    const int*   idx     = (const int*)  d_in[0];
    const int*   targets = (const int*)  d_in[1];
    const float* wte     = (const float*)d_in[2];
    const float* wpe     = (const float*)d_in[3];
    const float* ln1_w   = (const float*)d_in[4];
    const float* ln1_b   = (const float*)d_in[5];
    const float* attn_w  = (const float*)d_in[6];
    const float* attn_b  = (const float*)d_in[7];
    const float* proj_w  = (const float*)d_in[8];
    const float* proj_b  = (const float*)d_in[9];
    const float* ln2_w   = (const float*)d_in[10];
    const float* ln2_b   = (const float*)d_in[11];
    const float* fc_w    = (const float*)d_in[12];
    const float* fc_b    = (const float*)d_in[13];
    const float* out_w   = (const float*)d_in[14];
    const float* out_b   = (const float*)d_in[15];
    const float* lnf_w   = (const float*)d_in[16];
    const float* lnf_b   = (const float*)d_in[17];
    float* out = (float*)d_out;

    float *x, *h, *qkv, *y, *fc;
    cudaGetSymbolAddress((void**)&x,   g_x);
    cudaGetSymbolAddress((void**)&h,   g_h);
    cudaGetSymbolAddress((void**)&qkv, g_qkv);
    cudaGetSymbolAddress((void**)&y,   g_y);
    cudaGetSymbolAddress((void**)&fc,  g_fc);

    cudaFuncSetAttribute(flash_attn,
                         cudaFuncAttributeMaxDynamicSharedMemorySize, FATT_SMEM);

    embed_kernel<<<(M_ * E_) / 256, 256>>>(idx, wte, wpe);

    for (int l = 0; l < L_; l++) {
        ln_kernel<<<M_, 256>>>(x, ln1_w + (size_t)l * E_, ln1_b + (size_t)l * E_, h);
        gemm_tf32<<<gemm_grid(M_, E3_), 256>>>(
            h, attn_w + (size_t)l * E3_ * E_, attn_b + (size_t)l * E3_,
            nullptr, qkv, M_, E3_, E_, 0);
        flash_attn<<<dim3(T_ / 64, B_ * H_), 128, FATT_SMEM>>>(qkv, y);
        gemm_tf32<<<gemm_grid(M_, E_), 256>>>(
            y, proj_w + (size_t)l * E_ * E_, proj_b + (size_t)l * E_,
            x, x, M_, E_, E_, 0);
        ln_kernel<<<M_, 256>>>(x, ln2_w + (size_t)l * E_, ln2_b + (size_t)l * E_, h);
        gemm_tf32<<<gemm_grid(M_, E4_), 256>>>(
            h, fc_w + (size_t)l * E4_ * E_, fc_b + (size_t)l * E4_,
            nullptr, fc, M_, E4_, E_, 1);
        gemm_tf32<<<gemm_grid(M_, E_), 256>>>(
            fc, out_w + (size_t)l * E_ * E4_, out_b + (size_t)l * E_,
            x, x, M_, E_, E4_, 0);
    }

    ln_kernel<<<M_, 256>>>(x, lnf_w, lnf_b, h);
    gemm_tf32<<<gemm_grid(M_, V_), 256>>>(
        h, wte, nullptr, nullptr, out, M_, V_, E_, 0);

    loss_rows<<<B_ * (T_ - 1), 256>>>(out, targets);
    long long pos = (long long)M_ * V_;
    if (pos < (long long)out_size)
        loss_final<<<1, 256>>>(out, pos);
}

// round 4
// speedup vs baseline: 3.7467x; 1.1857x over previous
#include <cuda_runtime.h>
#include <math.h>

#define L_ 4
#define H_ 12
#define E_ 768
#define T_ 1024
#define B_ 4
#define V_ 50257
#define D_ 64
#define M_ (B_*T_)     // 4096
#define E3_ (3*E_)     // 2304
#define E4_ (4*E_)     // 3072

// ---------------- scratch (static device globals; no allocation) ----------
__device__ float g_x  [(size_t)M_*E_];
__device__ float g_h  [(size_t)M_*E_];
__device__ float g_qkv[(size_t)M_*E3_];
__device__ float g_y  [(size_t)M_*E_];
__device__ float g_fc [(size_t)M_*E4_];
__device__ float g_logp[B_*(T_-1)];

// ---------------- reductions ----------------------------------------------
__device__ __forceinline__ float blockReduceSum(float v, float* red) {
    int lane = threadIdx.x & 31, wid = threadIdx.x >> 5;
    #pragma unroll
    for (int o = 16; o; o >>= 1) v += __shfl_down_sync(0xffffffffu, v, o);
    __syncthreads();
    if (lane == 0) red[wid] = v;
    __syncthreads();
    if (threadIdx.x == 0) {
        float s = 0.f;
        int nw = (blockDim.x + 31) >> 5;
        for (int i = 0; i < nw; i++) s += red[i];
        red[0] = s;
    }
    __syncthreads();
    return red[0];
}

// ---------------- tf32 helpers ---------------------------------------------
__device__ __forceinline__ float to_tf32(float f) {
    unsigned r;
    asm("cvt.rna.tf32.f32 %0, %1;" : "=r"(r) : "f"(f));
    return __uint_as_float(r);
}

__device__ __forceinline__ unsigned f2tf32(float f) {
    unsigned r;
    asm("cvt.rna.tf32.f32 %0, %1;" : "=r"(r) : "f"(f));
    return r;
}

__device__ __forceinline__ void split_tf32(float x, unsigned& hi, unsigned& lo) {
    float h = to_tf32(x);
    hi = __float_as_uint(h);
    lo = __float_as_uint(to_tf32(x - h));
}

#define MMA_TF32(acc, a0,a1,a2,a3, b0,b1)                                   \
    asm volatile(                                                            \
        "mma.sync.aligned.m16n8k8.row.col.f32.tf32.tf32.f32 "               \
        "{%0,%1,%2,%3}, {%4,%5,%6,%7}, {%8,%9}, {%0,%1,%2,%3};"             \
        : "+f"((acc)[0]), "+f"((acc)[1]), "+f"((acc)[2]), "+f"((acc)[3])    \
        : "r"(a0), "r"(a1), "r"(a2), "r"(a3), "r"(b0), "r"(b1))

// ---------------- embedding -----------------------------------------------
__global__ void embed_kernel(const int* __restrict__ idx,
                             const float* __restrict__ wte,
                             const float* __restrict__ wpe) {
    int i = blockIdx.x * 256 + threadIdx.x;
    int bt = i / E_, e = i - bt * E_;
    int t = bt & (T_ - 1);
    g_x[i] = wte[(size_t)idx[bt] * E_ + e] + wpe[(size_t)t * E_ + e];
}

// ---------------- layernorm -----------------------------------------------
__global__ void ln_kernel(const float* __restrict__ in,
                          const float* __restrict__ w,
                          const float* __restrict__ b,
                          float* __restrict__ out) {
    int row = blockIdx.x;
    const float* x = in + (size_t)row * E_;
    __shared__ float sdata[E_];
    __shared__ float red[32];
    __shared__ float s_mean, s_rstd;
    float local = 0.f;
    for (int i = threadIdx.x; i < E_; i += 256) { float v = x[i]; sdata[i] = v; local += v; }
    float tot = blockReduceSum(local, red);
    if (threadIdx.x == 0) s_mean = tot * (1.0f / E_);
    __syncthreads();
    float m = s_mean, lv = 0.f;
    for (int i = threadIdx.x; i < E_; i += 256) { float d = sdata[i] - m; lv += d * d; }
    float var = blockReduceSum(lv, red);
    if (threadIdx.x == 0) s_rstd = rsqrtf(var * (1.0f / E_) + 1e-5f);
    __syncthreads();
    float r = s_rstd;
    float* o = out + (size_t)row * E_;
    for (int i = threadIdx.x; i < E_; i += 256)
        o[i] = (sdata[i] - m) * r * w[i] + b[i];
}

// ---------------- TF32 GEMM: C = A[MxK] * B[NxK]^T --------------------------
// 128x128x16 tile, 256 threads (2m x 4n warps, 64x32 warp tile),
// 4-stage cp.async pipeline, m-major smem with chunk-XOR swizzle.
#define STAGES 4
#define GEMM_SMEM (STAGES * 128 * 16 * 4 * 2)

__global__ __launch_bounds__(256, 2)
void gemm_tf32(const float* __restrict__ A, const float* __restrict__ B,
               const float* __restrict__ bias, const float* __restrict__ res,
               float* __restrict__ C, int M, int N, int K, int gelu) {
    extern __shared__ float smem[];
    float* As = smem;                       // [STAGES][128*16]
    float* Bs = smem + STAGES * 2048;

    int nbn = (N + 127) >> 7;
    int bid = blockIdx.x;
    int bpg = 8 * nbn;                      // 8 m-rows per L2 group
    int grp = bid / bpg, rr0 = bid % bpg;
    int m0 = (grp * 8 + (rr0 & 7)) << 7;
    int n0 = (rr0 >> 3) << 7;

    int tid = threadIdx.x;
    int lane = tid & 31, wid = tid >> 5;
    int wm = wid >> 2, wn = wid & 3;        // 2 x 4 warps
    int la = lane & 3, lg = lane >> 2;
    int sw = (lg >> 1) & 3;                 // frag-load swizzle constant

    // load mapping: thread handles 16B chunks 2*tid and 2*tid+1 (chunk = m*4+c)
    int gch = 2 * tid;
    int lm = gch >> 2, lc = gch & 3;        // lc in {0,2}; also lc+1
    int lsw = (lm >> 1) & 3;
    int soff0 = lm * 16 + ((lc ^ lsw) << 2);
    int soff1 = lm * 16 + (((lc + 1) ^ lsw) << 2);
    const float* gA = A + (size_t)(m0 + lm) * K + lc * 4;
    int bn = n0 + lm;
    int bok = (bn < N) ? 16 : 0;
    const float* gB = B + (size_t)(bok ? bn : 0) * K + lc * 4;
    unsigned sAb = (unsigned)__cvta_generic_to_shared(As);
    unsigned sBb = (unsigned)__cvta_generic_to_shared(Bs);

    auto issue = [&](int stage, int kb) {
        unsigned d0 = sAb + (unsigned)(stage * 2048 + soff0) * 4u;
        unsigned d1 = sAb + (unsigned)(stage * 2048 + soff1) * 4u;
        unsigned e0 = sBb + (unsigned)(stage * 2048 + soff0) * 4u;
        unsigned e1 = sBb + (unsigned)(stage * 2048 + soff1) * 4u;
        const float* pa = gA + kb;
        const float* pb = gB + kb;
        asm volatile("cp.async.cg.shared.global [%0], [%1], 16;" :: "r"(d0), "l"(pa));
        asm volatile("cp.async.cg.shared.global [%0], [%1], 16;" :: "r"(d1), "l"(pa + 4));
        asm volatile("cp.async.cg.shared.global [%0], [%1], 16, %2;" :: "r"(e0), "l"(pb), "r"(bok));
        asm volatile("cp.async.cg.shared.global [%0], [%1], 16, %2;" :: "r"(e1), "l"(pb + 4), "r"(bok));
    };

    float acc[4][4][4];
    #pragma unroll
    for (int i = 0; i < 4; i++)
        #pragma unroll
        for (int j = 0; j < 4; j++)
            #pragma unroll
            for (int k = 0; k < 4; k++) acc[i][j][k] = 0.f;

    int nk = K >> 4;
    issue(0, 0);  asm volatile("cp.async.commit_group;");
    issue(1, 16); asm volatile("cp.async.commit_group;");
    issue(2, 32); asm volatile("cp.async.commit_group;");

    for (int kt = 0; kt < nk; kt++) {
        asm volatile("cp.async.wait_group %0;" :: "n"(STAGES - 2));
        __syncthreads();
        int pf = kt + STAGES - 1;
        if (pf < nk) issue(pf & (STAGES - 1), pf << 4);
        asm volatile("cp.async.commit_group;");

        const float* as = As + (kt & (STAGES - 1)) * 2048;
        const float* bs = Bs + (kt & (STAGES - 1)) * 2048;

        #pragma unroll
        for (int ks = 0; ks < 16; ks += 8) {
            int c0 = ks >> 2;
            int colA = ((c0 ^ sw) << 2) + la;          // k = ks+la
            int colB = (((c0 + 1) ^ sw) << 2) + la;    // k = ks+la+4
            unsigned af[4][4], bf[4][2];
            #pragma unroll
            for (int mt = 0; mt < 4; mt++) {
                int mb = (wm * 64 + mt * 16 + lg) * 16;
                af[mt][0] = f2tf32(as[mb + colA]);
                af[mt][1] = f2tf32(as[mb + 128 + colA]);   // +8 rows
                af[mt][2] = f2tf32(as[mb + colB]);
                af[mt][3] = f2tf32(as[mb + 128 + colB]);
            }
            #pragma unroll
            for (int nt = 0; nt < 4; nt++) {
                int nb = (wn * 32 + nt * 8 + lg) * 16;
                bf[nt][0] = f2tf32(bs[nb + colA]);
                bf[nt][1] = f2tf32(bs[nb + colB]);
            }
            #pragma unroll
            for (int mt = 0; mt < 4; mt++)
                #pragma unroll
                for (int nt = 0; nt < 4; nt++)
                    MMA_TF32(acc[mt][nt], af[mt][0], af[mt][1], af[mt][2], af[mt][3],
                             bf[nt][0], bf[nt][1]);
        }
    }

    // epilogue
    #pragma unroll
    for (int mt = 0; mt < 4; mt++) {
        int rbase = m0 + wm * 64 + mt * 16 + lg;
        #pragma unroll
        for (int nt = 0; nt < 4; nt++) {
            int cbase = n0 + wn * 32 + nt * 8 + la * 2;
            #pragma unroll
            for (int half = 0; half < 2; half++) {
                int rw = rbase + half * 8;
                #pragma unroll
                for (int cc = 0; cc < 2; cc++) {
                    int c = cbase + cc;
                    if (c < N) {
                        float v = acc[mt][nt][half * 2 + cc];
                        if (bias) v += bias[c];
                        if (gelu) {
                            float t = v;
                            v = 0.5f * t * (1.0f + tanhf(0.7978845608028654f *
                                    (t + 0.044715f * t * t * t)));
                        }
                        size_t off = (size_t)rw * N + c;
                        if (res) v += res[off];
                        C[off] = v;
                    }
                }
            }
        }
    }
}

// ---------------- fused flash attention (3xTF32 mma, online softmax) -------
#define FATT_SMEM ((4 * 64 * 68 + 3 * 64) * 4)

__global__ __launch_bounds__(128)
void flash_attn(const float* __restrict__ qkv, float* __restrict__ y) {
    extern __shared__ float fsm[];
    float (*Qs)[68] = (float(*)[68])(fsm);
    float (*Ks)[68] = (float(*)[68])(fsm + 64 * 68);
    float (*Vs)[68] = (float(*)[68])(fsm + 2 * 64 * 68);
    float (*Ps)[68] = (float(*)[68])(fsm + 3 * 64 * 68);
    float* m_s = fsm + 4 * 64 * 68;
    float* l_s = m_s + 64;
    float* alpha_s = l_s + 64;

    int bh = blockIdx.y;
    int b = bh / H_, h = bh % H_;
    int q0 = blockIdx.x * 64;
    int tid = threadIdx.x;
    int lane = tid & 31, wm = tid >> 5;
    int la = lane & 3, lg = lane >> 2;

    #pragma unroll
    for (int i = 0; i < 8; i++) {
        int f4 = tid + i * 128;
        int row = f4 >> 4, c = (f4 & 15) << 2;
        *(float4*)&Qs[row][c] =
            *(const float4*)(qkv + (size_t)(b * T_ + q0 + row) * E3_ + h * D_ + c);
    }
    if (tid < 64) { m_s[tid] = -1e30f; l_s[tid] = 0.f; }

    float acc_o[8][4];
    #pragma unroll
    for (int i = 0; i < 8; i++)
        #pragma unroll
        for (int j = 0; j < 4; j++) acc_o[i][j] = 0.f;

    int row0 = wm * 16 + lg;
    int row1 = row0 + 8;

    int ktiles = (q0 >> 6) + 1;
    for (int kt = 0; kt < ktiles; kt++) {
        int k0 = kt << 6;
        __syncthreads();
        #pragma unroll
        for (int i = 0; i < 8; i++) {
            int f4 = tid + i * 128;
            int row = f4 >> 4, c = (f4 & 15) << 2;
            const float* base = qkv + (size_t)(b * T_ + k0 + row) * E3_ + h * D_ + c;
            *(float4*)&Ks[row][c] = *(const float4*)(base + E_);
            *(float4*)&Vs[row][c] = *(const float4*)(base + 2 * E_);
        }
        __syncthreads();

        float acc_s[8][4];
        #pragma unroll
        for (int i = 0; i < 8; i++)
            #pragma unroll
            for (int j = 0; j < 4; j++) acc_s[i][j] = 0.f;

        #pragma unroll
        for (int ks = 0; ks < 64; ks += 8) {
            unsigned ah[4], al[4];
            split_tf32(Qs[row0][ks + la    ], ah[0], al[0]);
            split_tf32(Qs[row1][ks + la    ], ah[1], al[1]);
            split_tf32(Qs[row0][ks + la + 4], ah[2], al[2]);
            split_tf32(Qs[row1][ks + la + 4], ah[3], al[3]);
            #pragma unroll
            for (int nt = 0; nt < 8; nt++) {
                int cb = nt * 8;
                unsigned bh0, bl0, bh1, bl1;
                split_tf32(Ks[cb + lg][ks + la    ], bh0, bl0);
                split_tf32(Ks[cb + lg][ks + la + 4], bh1, bl1);
                MMA_TF32(acc_s[nt], al[0], al[1], al[2], al[3], bh0, bh1);
                MMA_TF32(acc_s[nt], ah[0], ah[1], ah[2], ah[3], bl0, bl1);
                MMA_TF32(acc_s[nt], ah[0], ah[1], ah[2], ah[3], bh0, bh1);
            }
        }
        #pragma unroll
        for (int nt = 0; nt < 8; nt++) {
            int cb = nt * 8 + 2 * la;
            #pragma unroll
            for (int rr = 0; rr < 2; rr++) {
                int rloc = rr ? row1 : row0;
                int grow = q0 + rloc;
                #pragma unroll
                for (int cc = 0; cc < 2; cc++) {
                    int gcol = k0 + cb + cc;
                    float v = acc_s[nt][rr * 2 + cc] * 0.125f;
                    if (gcol > grow) v = -1e30f;
                    Ps[rloc][cb + cc] = v;
                }
            }
        }
        __syncthreads();

        {
            int r = tid >> 1, half = tid & 1;
            int c0 = half * 32;
            float mx = -1e30f;
            #pragma unroll 8
            for (int c = 0; c < 32; c++) mx = fmaxf(mx, Ps[r][c0 + c]);
            mx = fmaxf(mx, __shfl_xor_sync(0xffffffffu, mx, 1));
            float m_new = fmaxf(m_s[r], mx);
            float s = 0.f;
            #pragma unroll 8
            for (int c = 0; c < 32; c++) {
                float p = __expf(Ps[r][c0 + c] - m_new);
                Ps[r][c0 + c] = p;
                s += p;
            }
            s += __shfl_xor_sync(0xffffffffu, s, 1);
            if (half == 0) {
                float alpha = __expf(m_s[r] - m_new);
                l_s[r] = l_s[r] * alpha + s;
                m_s[r] = m_new;
                alpha_s[r] = alpha;
            }
        }
        __syncthreads();

        {
            float a0 = alpha_s[row0], a1 = alpha_s[row1];
            #pragma unroll
            for (int nt = 0; nt < 8; nt++) {
                acc_o[nt][0] *= a0; acc_o[nt][1] *= a0;
                acc_o[nt][2] *= a1; acc_o[nt][3] *= a1;
            }
        }
        #pragma unroll
        for (int ks = 0; ks < 64; ks += 8) {
            unsigned ah[4], al[4];
            split_tf32(Ps[row0][ks + la    ], ah[0], al[0]);
            split_tf32(Ps[row1][ks + la    ], ah[1], al[1]);
            split_tf32(Ps[row0][ks + la + 4], ah[2], al[2]);
            split_tf32(Ps[row1][ks + la + 4], ah[3], al[3]);
            #pragma unroll
            for (int nt = 0; nt < 8; nt++) {
                int cb = nt * 8;
                unsigned bh0, bl0, bh1, bl1;
                split_tf32(Vs[ks + la    ][cb + lg], bh0, bl0);
                split_tf32(Vs[ks + la + 4][cb + lg], bh1, bl1);
                MMA_TF32(acc_o[nt], al[0], al[1], al[2], al[3], bh0, bh1);
                MMA_TF32(acc_o[nt], ah[0], ah[1], ah[2], ah[3], bl0, bl1);
                MMA_TF32(acc_o[nt], ah[0], ah[1], ah[2], ah[3], bh0, bh1);
            }
        }
    }

    float inv0 = 1.0f / l_s[row0];
    float inv1 = 1.0f / l_s[row1];
    size_t yb0 = (size_t)(b * T_ + q0 + row0) * E_ + h * D_;
    size_t yb1 = (size_t)(b * T_ + q0 + row1) * E_ + h * D_;
    #pragma unroll
    for (int nt = 0; nt < 8; nt++) {
        int cb = nt * 8 + 2 * la;
        y[yb0 + cb    ] = acc_o[nt][0] * inv0;
        y[yb0 + cb + 1] = acc_o[nt][1] * inv0;
        y[yb1 + cb    ] = acc_o[nt][2] * inv1;
        y[yb1 + cb + 1] = acc_o[nt][3] * inv1;
    }
}

// ---------------- loss (single-pass online softmax) ------------------------
__global__ void loss_rows(const float* __restrict__ logits,
                          const int* __restrict__ targets) {
    int r = blockIdx.x;
    int b = r / (T_ - 1), t = r % (T_ - 1);
    const float* row = logits + (size_t)(b * T_ + t) * V_;
    int label = targets[b * T_ + t + 1];
    float mx = -1e30f, s = 0.f;
    for (int i = threadIdx.x; i < V_; i += 256) {
        float v = row[i];
        float mN = fmaxf(mx, v);
        s = s * __expf(mx - mN) + __expf(v - mN);
        mx = mN;
    }
    #pragma unroll
    for (int o = 16; o; o >>= 1) {
        float m2 = __shfl_down_sync(0xffffffffu, mx, o);
        float s2 = __shfl_down_sync(0xffffffffu, s, o);
        float mN = fmaxf(mx, m2);
        s = s * __expf(mx - mN) + s2 * __expf(m2 - mN);
        mx = mN;
    }
    __shared__ float smx[8], ssm[8];
    int lane = threadIdx.x & 31, wid = threadIdx.x >> 5;
    if (lane == 0) { smx[wid] = mx; ssm[wid] = s; }
    __syncthreads();
    if (threadIdx.x == 0) {
        float Mv = smx[0], Sv = ssm[0];
        #pragma unroll
        for (int i = 1; i < 8; i++) {
            float mN = fmaxf(Mv, smx[i]);
            Sv = Sv * __expf(Mv - mN) + ssm[i] * __expf(smx[i] - mN);
            Mv = mN;
        }
        g_logp[r] = row[label] - Mv - logf(Sv);
    }
}

__global__ void loss_final(float* __restrict__ out, long long pos) {
    __shared__ float red[32];
    float s = 0.f;
    for (int i = threadIdx.x; i < B_ * (T_ - 1); i += 256) s += g_logp[i];
    s = blockReduceSum(s, red);
    if (threadIdx.x == 0) out[pos] = -s / (float)(B_ * (T_ - 1));
}

// ---------------- driver ----------------------------------------------------
static inline int gemm_grid(int M, int N) {
    return (M >> 7) * ((N + 127) >> 7);
}

extern "C" void kernel_launch(void* const* d_in, const int* in_sizes, int n_in,
                              void* d_out, int out_size) {
    const int*   idx     = (const int*)  d_in[0];
    const int*   targets = (const int*)  d_in[1];
    const float* wte     = (const float*)d_in[2];
    const float* wpe     = (const float*)d_in[3];
    const float* ln1_w   = (const float*)d_in[4];
    const float* ln1_b   = (const float*)d_in[5];
    const float* attn_w  = (const float*)d_in[6];
    const float* attn_b  = (const float*)d_in[7];
    const float* proj_w  = (const float*)d_in[8];
    const float* proj_b  = (const float*)d_in[9];
    const float* ln2_w   = (const float*)d_in[10];
    const float* ln2_b   = (const float*)d_in[11];
    const float* fc_w    = (const float*)d_in[12];
    const float* fc_b    = (const float*)d_in[13];
    const float* out_w   = (const float*)d_in[14];
    const float* out_b   = (const float*)d_in[15];
    const float* lnf_w   = (const float*)d_in[16];
    const float* lnf_b   = (const float*)d_in[17];
    float* out = (float*)d_out;

    float *x, *h, *qkv, *y, *fc;
    cudaGetSymbolAddress((void**)&x,   g_x);
    cudaGetSymbolAddress((void**)&h,   g_h);
    cudaGetSymbolAddress((void**)&qkv, g_qkv);
    cudaGetSymbolAddress((void**)&y,   g_y);
    cudaGetSymbolAddress((void**)&fc,  g_fc);

    cudaFuncSetAttribute(flash_attn,
                         cudaFuncAttributeMaxDynamicSharedMemorySize, FATT_SMEM);
    cudaFuncSetAttribute(gemm_tf32,
                         cudaFuncAttributeMaxDynamicSharedMemorySize, GEMM_SMEM);

    embed_kernel<<<(M_ * E_) / 256, 256>>>(idx, wte, wpe);

    for (int l = 0; l < L_; l++) {
        ln_kernel<<<M_, 256>>>(x, ln1_w + (size_t)l * E_, ln1_b + (size_t)l * E_, h);
        gemm_tf32<<<gemm_grid(M_, E3_), 256, GEMM_SMEM>>>(
            h, attn_w + (size_t)l * E3_ * E_, attn_b + (size_t)l * E3_,
            nullptr, qkv, M_, E3_, E_, 0);
        flash_attn<<<dim3(T_ / 64, B_ * H_), 128, FATT_SMEM>>>(qkv, y);
        gemm_tf32<<<gemm_grid(M_, E_), 256, GEMM_SMEM>>>(
            y, proj_w + (size_t)l * E_ * E_, proj_b + (size_t)l * E_,
            x, x, M_, E_, E_, 0);
        ln_kernel<<<M_, 256>>>(x, ln2_w + (size_t)l * E_, ln2_b + (size_t)l * E_, h);
        gemm_tf32<<<gemm_grid(M_, E4_), 256, GEMM_SMEM>>>(
            h, fc_w + (size_t)l * E4_ * E_, fc_b + (size_t)l * E4_,
            nullptr, fc, M_, E4_, E_, 1);
        gemm_tf32<<<gemm_grid(M_, E_), 256, GEMM_SMEM>>>(
            fc, out_w + (size_t)l * E_ * E4_, out_b + (size_t)l * E_,
            x, x, M_, E_, E4_, 0);
    }

    ln_kernel<<<M_, 256>>>(x, lnf_w, lnf_b, h);
    gemm_tf32<<<gemm_grid(M_, V_), 256, GEMM_SMEM>>>(
        h, wte, nullptr, nullptr, out, M_, V_, E_, 0);

    loss_rows<<<B_ * (T_ - 1), 256>>>(out, targets);
    long long pos = (long long)M_ * V_;
    if (pos < (long long)out_size)
        loss_final<<<1, 256>>>(out, pos);
}